// round 17
// baseline (speedup 1.0000x reference)
#include <cuda_runtime.h>
#include <cstdint>

typedef unsigned long long ull;

// ---------------- packed f32x2 helpers (Blackwell FFMA2 path) ---------------
__device__ __forceinline__ ull pack2(float lo, float hi) {
    ull r; asm("mov.b64 %0, {%1, %2};" : "=l"(r) : "f"(lo), "f"(hi)); return r;
}
__device__ __forceinline__ ull dup2(float v) {
    ull r; asm("mov.b64 %0, {%1, %1};" : "=l"(r) : "f"(v)); return r;
}
__device__ __forceinline__ void unpack2(ull v, float& lo, float& hi) {
    asm("mov.b64 {%0, %1}, %2;" : "=f"(lo), "=f"(hi) : "l"(v));
}
__device__ __forceinline__ ull fma2(ull a, ull b, ull c) {
    ull d; asm("fma.rn.f32x2 %0, %1, %2, %3;" : "=l"(d) : "l"(a), "l"(b), "l"(c)); return d;
}
__device__ __forceinline__ void cp_async16(unsigned int saddr, const void* gptr, int src_sz) {
    asm volatile("cp.async.cg.shared.global [%0], [%1], 16, %2;"
                 :: "r"(saddr), "l"(gptr), "r"(src_sz));
}
__device__ __forceinline__ void cp_commit() { asm volatile("cp.async.commit_group;"); }
__device__ __forceinline__ void cp_wait0()  { asm volatile("cp.async.wait_group 0;"); }

// 9-tap accumulate macro: packed weight W applied to 2x2 conv positions
#define K9(W, KY, KX)                                   \
    a0 = fma2(pd[(KY)][(KX)],         (W), a0);         \
    a1 = fma2(pd[(KY)][(KX) + 1],     (W), a1);         \
    a2 = fma2(pd[(KY) + 1][(KX)],     (W), a2);         \
    a3 = fma2(pd[(KY) + 1][(KX) + 1], (W), a3);

#define NBLK 296
#define NTILE 1536

// ---------------- dynamic tile queue ----------------------------------------
__device__ int g_ctr;
__global__ void reset_kernel() { if (threadIdx.x == 0) g_ctr = 0; }

// x-halo staging prefetch for tile (img, by0, bx0) into xst (140 rows x 144 cols).
// All 16B chunks fully in-bounds or fully OOB (zero-filled) -- no straddles.
#define PREFETCH_X(IMG, BY0, BX0)                                             \
    {                                                                         \
        const float* xb = x + (size_t)(IMG) * 262144;                         \
        int ry0 = 4 * (BY0) - 6;                                              \
        int xc0a = (4 * (BX0) - 6) & ~3;                                      \
        for (int idx = tid; idx < 140 * 36; idx += 512) {                     \
            int rr = idx / 36, j = idx - rr * 36;                             \
            int gr = ry0 + rr, gc = xc0a + 4 * j;                             \
            bool ok = ((unsigned)gr < 512u) && ((unsigned)gc < 512u);         \
            const float* src = ok ? (xb + (size_t)gr * 512 + gc) : xb;        \
            cp_async16(xst_s + (unsigned int)(rr * 144 + 4 * j) * 4u, src,    \
                       ok ? 16 : 0);                                          \
        }                                                                     \
        cp_commit();                                                          \
    }

// ---------------- Single persistent fused kernel ----------------------------
// grid 296 (2/SM), block 512. Dynamic tile claiming via g_ctr.
// Per tile: wait xst -> phase0 DWT (paired cols, float4 loads, edges folded)
// -> phase1 conv1+pool -> ins -> phase2 conv2+pool (unroll 4; claims next
// tile) -> conv3 -> prefetch next x.
__global__ void __launch_bounds__(512, 2)
fused_all_kernel(const float* __restrict__ x,
                 const float* __restrict__ w1, const float* __restrict__ b1,
                 const float* __restrict__ w2, const float* __restrict__ b2,
                 const float* __restrict__ w3, const float* __restrict__ b3,
                 float* __restrict__ out_low, float* __restrict__ out_high) {
    extern __shared__ float sm[];
    float* cAt = sm;                       // 70 * 72 = 5040 floats
    float* ins = sm + 5040;                // max(140*144, 16*1224) = 20160 floats
    float* xst = ins;                      // x staging aliases ins
    ull*   w2p = (ull*)(ins + 20160);      // 640 ull (1280 fl)
    ull*   w1p = w2p + 640;                // 80 ull (160 fl)
    float* tail = (float*)(w1p + 80);
    ull*   b1p = (ull*)tail;               // 8 ull packed conv1 bias pairs
    ull*   b2p = (ull*)(tail + 16);        // 4 ull packed conv2 bias pairs
    float* w3s = tail + 24;                // 32
    float* b3s = tail + 56;                // 4
    float* v4buf = tail + 64;              // 2048 floats
    int*   flg = (int*)(tail + 64 + 2048); // [0]=initial claim, [1]=next claim

    int tid = threadIdx.x;                               // 512 threads
    unsigned int xst_s = (unsigned int)__cvta_generic_to_shared(xst);

    // ---- initial tile claim ----
    if (tid == 0) flg[0] = atomicAdd(&g_ctr, 1);
    __syncthreads();
    int tile = flg[0];

    // ---- prologue prefetch for first tile ----
    if (tile < NTILE) {
        int img0 = tile >> 4;
        int tt0 = tile & 15;
        int by00 = (tt0 >> 2) * 32, bx00 = (tt0 & 3) * 32;
        PREFETCH_X(img0, by00, bx00)
    }

    // ---- weights (once per block) ----
    if (tid < 80) {
        int op = tid / 10, k = tid - op * 10;
        w1p[tid] = (k < 9) ? pack2(w1[(2 * op) * 9 + k], w1[(2 * op + 1) * 9 + k]) : 0ull;
    }
    for (int i = tid; i < 640; i += 512) {
        int op = i / 160;
        int rem = i - op * 160;            // ic*10 + k
        int ic = rem / 10, k = rem - ic * 10;
        w2p[i] = (k < 9) ? pack2(w2[(2 * op) * 144 + ic * 9 + k],
                                 w2[(2 * op + 1) * 144 + ic * 9 + k]) : 0ull;
    }
    if (tid < 8) b1p[tid] = pack2(b1[2 * tid], b1[2 * tid + 1]);
    if (tid >= 8 && tid < 12) b2p[tid - 8] = pack2(b2[2 * (tid - 8)], b2[2 * (tid - 8) + 1]);
    if (tid < 32) w3s[tid] = w3[tid];
    if (tid < 4) b3s[tid] = b3[tid];

    while (tile < NTILE) {
        int img = tile >> 4;
        int tt = tile & 15;
        int by0 = (tt >> 2) * 32, bx0 = (tt & 3) * 32;   // conv2 origin in 128x128
        int cy0 = 2 * by0 - 3, cx0 = 2 * bx0 - 3;        // cA halo origin in 256x256

        cp_wait0();
        __syncthreads();                   // (a) xst staged; v4buf/flg free

        // ---- phase 0: Haar DWT from xst -> cAt + own cH/cV region ----
        // 70 rows x 35 units: u%35<34 -> col pair (2u%35+1, +1); u%35==34 ->
        // edge cols 0 and 69 (cAt only, never interior).
        {
            float* hb = out_high + (size_t)img * 131072;
            for (int u = tid; u < 70 * 35; u += 512) {
                int r = u / 35, cp = u - r * 35;
                if (cp < 34) {
                    int c = 2 * cp + 1;
                    const float* bp = xst + 2 * r * 144 + 2 * c + 2;
                    float4 t = *(const float4*)bp;
                    float4 bo = *(const float4*)(bp + 144);
                    cAt[r * 72 + c]     = (t.x + t.y + bo.x + bo.y) * 0.5f;
                    cAt[r * 72 + c + 1] = (t.z + t.w + bo.z + bo.w) * 0.5f;
                    if (r >= 3 && r < 67 && c >= 3 && c <= 65) {
                        float cH0 = (t.x + t.y - bo.x - bo.y) * 0.5f;
                        float cV0 = (t.x - t.y + bo.x - bo.y) * 0.5f;
                        float cH1 = (t.z + t.w - bo.z - bo.w) * 0.5f;
                        float cV1 = (t.z - t.w + bo.z - bo.w) * 0.5f;
                        int o = (cy0 + r) * 256 + (cx0 + c);   // even
                        *(float2*)(hb + o)         = make_float2(cH0, cH1);
                        *(float2*)(hb + 65536 + o) = make_float2(cV0, cV1);
                    }
                } else {
                    const float* bp0 = xst + 2 * r * 144 + 2;
                    float2 t0 = *(const float2*)bp0;
                    float2 b0 = *(const float2*)(bp0 + 144);
                    cAt[r * 72] = (t0.x + t0.y + b0.x + b0.y) * 0.5f;
                    const float* bp1 = xst + 2 * r * 144 + 140;
                    float2 t1 = *(const float2*)bp1;
                    float2 b1v = *(const float2*)(bp1 + 144);
                    cAt[r * 72 + 69] = (t1.x + t1.y + b1v.x + b1v.y) * 0.5f;
                }
            }
        }
        __syncthreads();                   // (b) cAt ready; xst consumed

        // ---- phase 1: t1 tile (34x34 positions x 16 ch) -> ins ----
        for (int pos = tid; pos < 34 * 34; pos += 512) {
            int r = pos / 34, c = pos - r * 34;
            int ty = by0 - 1 + r, tx = bx0 - 1 + c;       // global t1 coords
            float* op_out = ins + r * 36 + c;
            if ((unsigned)ty < 128u && (unsigned)tx < 128u) {
                const float* ip = cAt + 2 * r * 72 + 2 * c;
                ull pd[4][4];
#pragma unroll
                for (int rr = 0; rr < 4; rr++) {
                    float2 u0 = *(const float2*)(ip + rr * 72);
                    float2 u1 = *(const float2*)(ip + rr * 72 + 2);
                    pd[rr][0] = dup2(u0.x); pd[rr][1] = dup2(u0.y);
                    pd[rr][2] = dup2(u1.x); pd[rr][3] = dup2(u1.y);
                }
#pragma unroll
                for (int op = 0; op < 8; op++) {
                    ull bb = b1p[op];
                    ull a0 = bb, a1 = bb, a2 = bb, a3 = bb;
                    const ull* wp = w1p + op * 10;
                    ulonglong2 w01 = *(const ulonglong2*)wp;
                    ulonglong2 w23 = *(const ulonglong2*)(wp + 2);
                    ulonglong2 w45 = *(const ulonglong2*)(wp + 4);
                    ulonglong2 w67 = *(const ulonglong2*)(wp + 6);
                    ull w8 = wp[8];
                    K9(w01.x, 0, 0) K9(w01.y, 0, 1) K9(w23.x, 0, 2)
                    K9(w23.y, 1, 0) K9(w45.x, 1, 1) K9(w45.y, 1, 2)
                    K9(w67.x, 2, 0) K9(w67.y, 2, 1) K9(w8,    2, 2)
                    float s0l, s0h, s1l, s1h, s2l, s2h, s3l, s3h;
                    unpack2(a0, s0l, s0h); unpack2(a1, s1l, s1h);
                    unpack2(a2, s2l, s2h); unpack2(a3, s3l, s3h);
                    float ml = fmaxf(fmaxf(s0l, s1l), fmaxf(s2l, s3l));
                    float mh = fmaxf(fmaxf(s0h, s1h), fmaxf(s2h, s3h));
                    op_out[(2 * op) * 1224]     = fmaxf(ml, 0.f);
                    op_out[(2 * op + 1) * 1224] = fmaxf(mh, 0.f);
                }
            } else {
#pragma unroll
                for (int ic = 0; ic < 16; ic++) op_out[ic * 1224] = 0.f;
            }
        }
        __syncthreads();                   // (c) ins ready

        // ---- claim next tile (latency hidden under phase 2) ----
        if (tid == 0) flg[1] = atomicAdd(&g_ctr, 1);

        // ---- phase 2: conv2 + relu + pool (oc split across 2 groups) ----
        int pix = tid & 255, g = tid >> 8;
        int tyx = pix & 15, tyy = pix >> 4;
        int ly = 2 * tyy, lx = 2 * tyx;
        const ull* wg = w2p + (2 * g) * 160;
        ull acc[2][4];
#pragma unroll
        for (int op2 = 0; op2 < 2; op2++) {
            ull bb = b2p[2 * g + op2];
            acc[op2][0] = bb; acc[op2][1] = bb; acc[op2][2] = bb; acc[op2][3] = bb;
        }

#pragma unroll 4
        for (int ic = 0; ic < 16; ic++) {
            const float* ip = ins + ic * 1224 + ly * 36 + lx;
            ull pd[4][4];
#pragma unroll
            for (int rr = 0; rr < 4; rr++) {
                float2 u0 = *(const float2*)(ip + rr * 36);
                float2 u1 = *(const float2*)(ip + rr * 36 + 2);
                pd[rr][0] = dup2(u0.x); pd[rr][1] = dup2(u0.y);
                pd[rr][2] = dup2(u1.x); pd[rr][3] = dup2(u1.y);
            }
#pragma unroll
            for (int op2 = 0; op2 < 2; op2++) {
                const ull* wp = wg + op2 * 160 + ic * 10;
                ulonglong2 w01 = *(const ulonglong2*)wp;
                ulonglong2 w23 = *(const ulonglong2*)(wp + 2);
                ulonglong2 w45 = *(const ulonglong2*)(wp + 4);
                ulonglong2 w67 = *(const ulonglong2*)(wp + 6);
                ull w8 = wp[8];
                ull a0 = acc[op2][0], a1 = acc[op2][1], a2 = acc[op2][2], a3 = acc[op2][3];
                K9(w01.x, 0, 0) K9(w01.y, 0, 1) K9(w23.x, 0, 2)
                K9(w23.y, 1, 0) K9(w45.x, 1, 1) K9(w45.y, 1, 2)
                K9(w67.x, 2, 0) K9(w67.y, 2, 1) K9(w8,    2, 2)
                acc[op2][0] = a0; acc[op2][1] = a1; acc[op2][2] = a2; acc[op2][3] = a3;
            }
        }

        float v4[4];
#pragma unroll
        for (int op2 = 0; op2 < 2; op2++) {
            float s0l, s0h, s1l, s1h, s2l, s2h, s3l, s3h;
            unpack2(acc[op2][0], s0l, s0h); unpack2(acc[op2][1], s1l, s1h);
            unpack2(acc[op2][2], s2l, s2h); unpack2(acc[op2][3], s3l, s3h);
            float ml = fmaxf(fmaxf(s0l, s1l), fmaxf(s2l, s3l));
            float mh = fmaxf(fmaxf(s0h, s1h), fmaxf(s2h, s3h));
            v4[2 * op2]     = fmaxf(ml, 0.f);
            v4[2 * op2 + 1] = fmaxf(mh, 0.f);
        }
        *(float4*)(v4buf + pix * 8 + 4 * g) = make_float4(v4[0], v4[1], v4[2], v4[3]);
        __syncthreads();                   // (d) ins dead; v4buf + flg[1] ready

        int ntile = flg[1];

        // ---- phase 3: conv3 (8->4, 1x1): 512 threads, 2 outputs each ----
        {
            int p = tid >> 1;                    // pixel 0..255
            int half = (tid & 1) * 2;            // o3 in {half, half+1}
            float4 lo4 = *(const float4*)(v4buf + p * 8);
            float4 hi4 = *(const float4*)(v4buf + p * 8 + 4);
            float v8[8] = {lo4.x, lo4.y, lo4.z, lo4.w, hi4.x, hi4.y, hi4.z, hi4.w};
            int oy = (by0 >> 1) + (p >> 4);
            int ox = (bx0 >> 1) + (p & 15);
            float* ob = out_low + (size_t)img * 4 * 4096 + oy * 64 + ox;
#pragma unroll
            for (int j = 0; j < 2; j++) {
                int o3 = half + j;
                float s = b3s[o3];
#pragma unroll
                for (int ic = 0; ic < 8; ic++) s += v8[ic] * w3s[o3 * 8 + ic];
                ob[o3 * 4096] = s;
            }
        }

        // ---- prefetch next tile's x halo into ins ----
        if (ntile < NTILE) {
            int nimg = ntile >> 4;
            int ntt = ntile & 15;
            int nby = (ntt >> 2) * 32, nbx = (ntt & 3) * 32;
            PREFETCH_X(nimg, nby, nbx)
        }

        tile = ntile;
        // loop top: cp_wait0 + syncthreads orders xst staging & v4buf reuse
    }
}

// ---------------------------------------------------------------------------
extern "C" void kernel_launch(void* const* d_in, const int* in_sizes, int n_in,
                              void* d_out, int out_size) {
    const float* x  = (const float*)d_in[0];
    const float* w1 = (const float*)d_in[1];
    const float* b1 = (const float*)d_in[2];
    const float* w2 = (const float*)d_in[3];
    const float* b2 = (const float*)d_in[4];
    const float* w3 = (const float*)d_in[5];
    const float* b3 = (const float*)d_in[6];
    float* out = (float*)d_out;

    const int LOW_SIZE = 96 * 4 * 64 * 64;                               // 1,572,864
    const int SMEM_F = (5040 + 20160 + 1280 + 160 + 64 + 2048 + 4) * 4;  // 115,024 B

    cudaFuncSetAttribute(fused_all_kernel, cudaFuncAttributeMaxDynamicSharedMemorySize, SMEM_F);

    reset_kernel<<<1, 32>>>();
    fused_all_kernel<<<NBLK, 512, SMEM_F>>>(x, w1, b1, w2, b2, w3, b3,
                                            out, out + LOW_SIZE);
}